// round 1
// baseline (speedup 1.0000x reference)
#include <cuda_runtime.h>
#include <cstdint>

#define H      128
#define INW    86
#define OUTW   66
#define GATES  512
#define TSEQ   50
#define NSTEP  65   // 50 scan + 1 replay of x[:,49] + 14 rollout
#define RSTEPS 15
#define BT     32   // batch rows per block
#define PITCH  34   // padded row pitch (even, for 64-bit pair loads; 2k mod 32 bank spread)
#define NTHR   256

typedef unsigned long long ull;

// ---- weight scratch (transposed for coalesced per-gate-unit access) ----
__device__ float g_WT0 [INW * GATES];   // Wih0^T : [86][512]
__device__ float g_WhT0[H   * GATES];   // Whh0^T : [128][512]
__device__ float g_WT1 [H   * GATES];   // Wih1^T : [128][512]
__device__ float g_WhT1[H   * GATES];   // Whh1^T : [128][512]
__device__ float g_WdT [H * OUTW];      // Wd^T   : [128][66]
__device__ float g_b0[GATES];
__device__ float g_b1[GATES];

// ---- packed f32x2 helpers (Blackwell FFMA2 via PTX) ----
__device__ __forceinline__ ull splat2(float v){ ull r; asm("mov.b64 %0, {%1, %1};" : "=l"(r) : "f"(v)); return r; }
__device__ __forceinline__ ull pack2(float x, float y){ ull r; asm("mov.b64 %0, {%1, %2};" : "=l"(r) : "f"(x), "f"(y)); return r; }
__device__ __forceinline__ float2 unpack2(ull a){ float2 f; asm("mov.b64 {%0, %1}, %2;" : "=f"(f.x), "=f"(f.y) : "l"(a)); return f; }
__device__ __forceinline__ ull fma2(ull a, ull b, ull c){ ull d; asm("fma.rn.f32x2 %0, %1, %2, %3;" : "=l"(d) : "l"(a), "l"(b), "l"(c)); return d; }

__device__ __forceinline__ float sigf(float x){ return 1.0f / (1.0f + __expf(-x)); }

// Accumulate gates over K: acc[g][p] += src2[kk][pair p] * W[kk][g*128+k]
// src points at transposed smem [K][PITCH]; pair loads are warp-broadcast LDS.64.
template<int K>
__device__ __forceinline__ void accum(ull acc[4][8], const float* __restrict__ WT,
                                      const float* src, int k, int rbase)
{
  #pragma unroll 4
  for (int kk = 0; kk < K; ++kk) {
    const float* w = WT + kk * GATES + k;
    ull s0 = splat2(__ldg(w));
    ull s1 = splat2(__ldg(w + 128));
    ull s2 = splat2(__ldg(w + 256));
    ull s3 = splat2(__ldg(w + 384));
    const float* srow = src + kk * PITCH + rbase;
    #pragma unroll
    for (int p = 0; p < 8; ++p) {
      ull u2 = *reinterpret_cast<const ull*>(srow + 2 * p);
      acc[0][p] = fma2(u2, s0, acc[0][p]);
      acc[1][p] = fma2(u2, s1, acc[1][p]);
      acc[2][p] = fma2(u2, s2, acc[2][p]);
      acc[3][p] = fma2(u2, s3, acc[3][p]);
    }
  }
}

// i,f,g,o -> (c,h) update for 8 row-pairs; c in registers, h returned in hn.
__device__ __forceinline__ void cell_update(ull acc[4][8], ull cst[8], ull hn[8])
{
  #pragma unroll
  for (int p = 0; p < 8; ++p) {
    float2 gi = unpack2(acc[0][p]);
    float2 gf = unpack2(acc[1][p]);
    float2 gg = unpack2(acc[2][p]);
    float2 go = unpack2(acc[3][p]);
    float2 c  = unpack2(cst[p]);
    float cx = sigf(gf.x) * c.x + sigf(gi.x) * tanhf(gg.x);
    float cy = sigf(gf.y) * c.y + sigf(gi.y) * tanhf(gg.y);
    float hx = sigf(go.x) * tanhf(cx);
    float hy = sigf(go.y) * tanhf(cy);
    cst[p] = pack2(cx, cy);
    hn[p]  = pack2(hx, hy);
  }
}

// ---- weight transpose / bias fuse (tiny, once per launch) ----
__global__ void prep_kernel(const float* __restrict__ Wih0, const float* __restrict__ Whh0,
                            const float* __restrict__ bih0, const float* __restrict__ bhh0,
                            const float* __restrict__ Wih1, const float* __restrict__ Whh1,
                            const float* __restrict__ bih1, const float* __restrict__ bhh1,
                            const float* __restrict__ Wd)
{
  int j = blockIdx.x * blockDim.x + threadIdx.x;
  if (j < GATES * INW) { g_WT0[(j % INW) * GATES + (j / INW)] = Wih0[j]; return; }
  j -= GATES * INW;
  if (j < GATES * H) { g_WhT0[(j % H) * GATES + (j / H)] = Whh0[j]; return; }
  j -= GATES * H;
  if (j < GATES * H) { g_WT1[(j % H) * GATES + (j / H)] = Wih1[j]; return; }
  j -= GATES * H;
  if (j < GATES * H) { g_WhT1[(j % H) * GATES + (j / H)] = Whh1[j]; return; }
  j -= GATES * H;
  if (j < OUTW * H) { g_WdT[(j % H) * OUTW + (j / H)] = Wd[j]; return; }
  j -= OUTW * H;
  if (j < GATES) { g_b0[j] = bih0[j] + bhh0[j]; return; }
  j -= GATES;
  if (j < GATES) { g_b1[j] = bih1[j] + bhh1[j]; return; }
}

// ---- main persistent-tile LSTM kernel ----
// Block: 32 batch rows for all 65 steps. Thread (k = tid&127 gate unit, rg = tid>>7 row-group of 16 rows).
// Each thread computes 4 gates x 8 row-pairs with packed f32x2 FMAs; c-state lives in registers.
__global__ void __launch_bounds__(NTHR, 1)
lstm_main(const float* __restrict__ x, const float* __restrict__ bd, float* __restrict__ out)
{
  __shared__ __align__(16) float uT [INW][PITCH];  // transposed step input
  __shared__ __align__(16) float h1T[H][PITCH];
  __shared__ __align__(16) float h2T[H][PITCH];

  const int tid   = threadIdx.x;
  const int k     = tid & 127;
  const int rg    = tid >> 7;
  const int rbase = rg * 16;
  const int row0  = blockIdx.x * BT;

  for (int i = tid; i < H * PITCH; i += NTHR) { (&h1T[0][0])[i] = 0.0f; (&h2T[0][0])[i] = 0.0f; }

  ull c1[8], c2[8];
  #pragma unroll
  for (int p = 0; p < 8; ++p) { c1[p] = 0ull; c2[p] = 0ull; }

  float b0r[4], b1r[4];
  #pragma unroll
  for (int g = 0; g < 4; ++g) { b0r[g] = g_b0[g * 128 + k]; b1r[g] = g_b1[g * 128 + k]; }
  const float bdv = (k < OUTW) ? bd[k] : 0.0f;

  __syncthreads();

  for (int s = 0; s < NSTEP; ++s) {
    // ---- stage input u ----
    // s < 50: x[:, s, :].  s == 50: x[:, 49, :] again (also caches cond rows 66..85).
    // s > 50: uT[0..65] holds pose from previous step's dense; uT[66..85] keeps cond.
    if (s <= TSEQ) {
      int t = (s < TSEQ) ? s : (TSEQ - 1);
      for (int i = tid; i < BT * INW; i += NTHR) {
        int r = i / INW, c = i % INW;
        uT[c][r] = x[(size_t)(row0 + r) * (TSEQ * INW) + t * INW + c];
      }
    }
    __syncthreads();

    ull acc[4][8], hn[8];

    // ---- layer 0 : gates = u@Wih0^T + h1@Whh0^T + b0 ----
    #pragma unroll
    for (int g = 0; g < 4; ++g)
      #pragma unroll
      for (int p = 0; p < 8; ++p) acc[g][p] = splat2(b0r[g]);
    accum<INW>(acc, g_WT0,  &uT[0][0],  k, rbase);
    accum<H>  (acc, g_WhT0, &h1T[0][0], k, rbase);
    cell_update(acc, c1, hn);
    __syncthreads();                      // all reads of old h1T done
    #pragma unroll
    for (int p = 0; p < 8; ++p)
      *reinterpret_cast<ull*>(&h1T[k][rbase + 2 * p]) = hn[p];
    __syncthreads();

    // ---- layer 1 : gates = h1@Wih1^T + h2@Whh1^T + b1 ----
    #pragma unroll
    for (int g = 0; g < 4; ++g)
      #pragma unroll
      for (int p = 0; p < 8; ++p) acc[g][p] = splat2(b1r[g]);
    accum<H>(acc, g_WT1,  &h1T[0][0], k, rbase);
    accum<H>(acc, g_WhT1, &h2T[0][0], k, rbase);
    cell_update(acc, c2, hn);
    __syncthreads();                      // all reads of old h2T done
    #pragma unroll
    for (int p = 0; p < 8; ++p)
      *reinterpret_cast<ull*>(&h2T[k][rbase + 2 * p]) = hn[p];
    __syncthreads();

    // ---- dense head (steps 50..64): pose = h2 @ Wd^T + bd ----
    if (s >= TSEQ) {
      const int so = s - TSEQ;
      if (k < OUTW) {
        ull pa[8];
        #pragma unroll
        for (int p = 0; p < 8; ++p) pa[p] = splat2(bdv);
        #pragma unroll 4
        for (int kk = 0; kk < H; ++kk) {
          ull w2 = splat2(__ldg(&g_WdT[kk * OUTW + k]));
          const float* srow = &h2T[kk][rbase];
          #pragma unroll
          for (int p = 0; p < 8; ++p) {
            ull u2 = *reinterpret_cast<const ull*>(srow + 2 * p);
            pa[p] = fma2(u2, w2, pa[p]);
          }
        }
        #pragma unroll
        for (int p = 0; p < 8; ++p) {
          float2 f = unpack2(pa[p]);
          int rloc = rbase + 2 * p;
          size_t r = (size_t)(row0 + rloc);
          out[ r      * (RSTEPS * OUTW) + so * OUTW + k] = f.x;
          out[(r + 1) * (RSTEPS * OUTW) + so * OUTW + k] = f.y;
          uT[k][rloc]     = f.x;   // pose becomes next step's u[0..65]
          uT[k][rloc + 1] = f.y;
        }
      }
      __syncthreads();
    }
  }
}

extern "C" void kernel_launch(void* const* d_in, const int* in_sizes, int n_in,
                              void* d_out, int out_size)
{
  const float* x    = (const float*)d_in[0];
  const float* Wih0 = (const float*)d_in[1];
  const float* Whh0 = (const float*)d_in[2];
  const float* bih0 = (const float*)d_in[3];
  const float* bhh0 = (const float*)d_in[4];
  const float* Wih1 = (const float*)d_in[5];
  const float* Whh1 = (const float*)d_in[6];
  const float* bih1 = (const float*)d_in[7];
  const float* bhh1 = (const float*)d_in[8];
  const float* Wd   = (const float*)d_in[9];
  const float* bd   = (const float*)d_in[10];
  float* out = (float*)d_out;

  const int B = in_sizes[0] / (TSEQ * INW);   // 8192

  const int prep_n = GATES * INW + 3 * GATES * H + OUTW * H + 2 * GATES;
  prep_kernel<<<(prep_n + 255) / 256, 256>>>(Wih0, Whh0, bih0, bhh0,
                                             Wih1, Whh1, bih1, bhh1, Wd);
  lstm_main<<<B / BT, NTHR>>>(x, bd, out);
}

// round 2
// speedup vs baseline: 1.3269x; 1.3269x over previous
#include <cuda_runtime.h>
#include <cstdint>

#define H      128
#define INW    86
#define OUTW   66
#define GATES  512
#define TSEQ   50
#define NSTEP  65   // 50 scan + 1 replay of x[:,49] + 14 rollout
#define RSTEPS 15
#define BT     16   // batch rows per block
#define PITCH  20   // padded row pitch: multiple of 4 for 16B-aligned pair loads
#define NTHR   256

typedef unsigned long long ull;

// ---- weight scratch: gate-interleaved float4 [kk][k] = {w_i, w_f, w_g, w_o} ----
__device__ float4 g_W0i[INW * H];   // from Wih0 [512][86]
__device__ float4 g_W0h[H   * H];   // from Whh0 [512][128]
__device__ float4 g_W1i[H   * H];   // from Wih1 [512][128]
__device__ float4 g_W1h[H   * H];   // from Whh1 [512][128]
__device__ float  g_WdT[H * OUTW];  // Wd^T : [kk][o]
__device__ float  g_b0[GATES];
__device__ float  g_b1[GATES];

// ---- packed f32x2 helpers (Blackwell FFMA2 via PTX) ----
__device__ __forceinline__ ull splat2(float v){ ull r; asm("mov.b64 %0, {%1, %1};" : "=l"(r) : "f"(v)); return r; }
__device__ __forceinline__ ull pack2(float x, float y){ ull r; asm("mov.b64 %0, {%1, %2};" : "=l"(r) : "f"(x), "f"(y)); return r; }
__device__ __forceinline__ float2 unpack2(ull a){ float2 f; asm("mov.b64 {%0, %1}, %2;" : "=f"(f.x), "=f"(f.y) : "l"(a)); return f; }
__device__ __forceinline__ ull fma2(ull a, ull b, ull c){ ull d; asm("fma.rn.f32x2 %0, %1, %2, %3;" : "=l"(d) : "l"(a), "l"(b), "l"(c)); return d; }

// fast activations: sigma via EX2+RCP, tanh(x) = 2*sigma(2x) - 1  (~1e-6 err, no tanhf poly)
__device__ __forceinline__ float sigf(float x){ return __fdividef(1.0f, 1.0f + __expf(-x)); }
__device__ __forceinline__ float tanhfast(float x){ return __fdividef(2.0f, 1.0f + __expf(-2.0f * x)) - 1.0f; }

// Accumulate gates over K for 4 row-pairs.
// One LDG.128 fetches all 4 gate weights for unit k; smem rows read as broadcast LDS.128.
template<int K>
__device__ __forceinline__ void accum(ull acc[4][4], const float4* __restrict__ W4,
                                      const float* src, int k, int rbase)
{
  #pragma unroll 4
  for (int kk = 0; kk < K; ++kk) {
    float4 w = __ldg(W4 + kk * H + k);
    ull s0 = splat2(w.x), s1 = splat2(w.y), s2 = splat2(w.z), s3 = splat2(w.w);
    const float* srow = src + kk * PITCH + rbase;
    ulonglong2 ua = *reinterpret_cast<const ulonglong2*>(srow);
    ulonglong2 ub = *reinterpret_cast<const ulonglong2*>(srow + 4);
    acc[0][0] = fma2(ua.x, s0, acc[0][0]);
    acc[1][0] = fma2(ua.x, s1, acc[1][0]);
    acc[2][0] = fma2(ua.x, s2, acc[2][0]);
    acc[3][0] = fma2(ua.x, s3, acc[3][0]);
    acc[0][1] = fma2(ua.y, s0, acc[0][1]);
    acc[1][1] = fma2(ua.y, s1, acc[1][1]);
    acc[2][1] = fma2(ua.y, s2, acc[2][1]);
    acc[3][1] = fma2(ua.y, s3, acc[3][1]);
    acc[0][2] = fma2(ub.x, s0, acc[0][2]);
    acc[1][2] = fma2(ub.x, s1, acc[1][2]);
    acc[2][2] = fma2(ub.x, s2, acc[2][2]);
    acc[3][2] = fma2(ub.x, s3, acc[3][2]);
    acc[0][3] = fma2(ub.y, s0, acc[0][3]);
    acc[1][3] = fma2(ub.y, s1, acc[1][3]);
    acc[2][3] = fma2(ub.y, s2, acc[2][3]);
    acc[3][3] = fma2(ub.y, s3, acc[3][3]);
  }
}

// i,f,g,o -> (c,h) update for 4 row-pairs
__device__ __forceinline__ void cell_update(ull acc[4][4], ull cst[4], ull hn[4])
{
  #pragma unroll
  for (int p = 0; p < 4; ++p) {
    float2 gi = unpack2(acc[0][p]);
    float2 gf = unpack2(acc[1][p]);
    float2 gg = unpack2(acc[2][p]);
    float2 go = unpack2(acc[3][p]);
    float2 c  = unpack2(cst[p]);
    float cx = sigf(gf.x) * c.x + sigf(gi.x) * tanhfast(gg.x);
    float cy = sigf(gf.y) * c.y + sigf(gi.y) * tanhfast(gg.y);
    float hx = sigf(go.x) * tanhfast(cx);
    float hy = sigf(go.y) * tanhfast(cy);
    cst[p] = pack2(cx, cy);
    hn[p]  = pack2(hx, hy);
  }
}

// ---- weight rearrange / bias fuse (tiny, once per launch) ----
__global__ void prep_kernel(const float* __restrict__ Wih0, const float* __restrict__ Whh0,
                            const float* __restrict__ bih0, const float* __restrict__ bhh0,
                            const float* __restrict__ Wih1, const float* __restrict__ Whh1,
                            const float* __restrict__ bih1, const float* __restrict__ bhh1,
                            const float* __restrict__ Wd)
{
  int j = blockIdx.x * blockDim.x + threadIdx.x;
  // matrix scalar -> float4 component: row r = g*128+k, col kk
  if (j < GATES * INW) {
    int r = j / INW, kk = j % INW;
    reinterpret_cast<float*>(g_W0i)[(kk * H + (r & 127)) * 4 + (r >> 7)] = Wih0[j];
    return;
  }
  j -= GATES * INW;
  if (j < GATES * H) {
    int r = j / H, kk = j % H;
    reinterpret_cast<float*>(g_W0h)[(kk * H + (r & 127)) * 4 + (r >> 7)] = Whh0[j];
    return;
  }
  j -= GATES * H;
  if (j < GATES * H) {
    int r = j / H, kk = j % H;
    reinterpret_cast<float*>(g_W1i)[(kk * H + (r & 127)) * 4 + (r >> 7)] = Wih1[j];
    return;
  }
  j -= GATES * H;
  if (j < GATES * H) {
    int r = j / H, kk = j % H;
    reinterpret_cast<float*>(g_W1h)[(kk * H + (r & 127)) * 4 + (r >> 7)] = Whh1[j];
    return;
  }
  j -= GATES * H;
  if (j < OUTW * H) { g_WdT[(j % H) * OUTW + (j / H)] = Wd[j]; return; }
  j -= OUTW * H;
  if (j < GATES) { g_b0[j] = bih0[j] + bhh0[j]; return; }
  j -= GATES;
  if (j < GATES) { g_b1[j] = bih1[j] + bhh1[j]; return; }
}

// ---- main persistent-tile LSTM kernel ----
// Block: 16 batch rows for all 65 steps; 2 blocks/SM (16 warps) for latency hiding.
// Thread (k = tid&127 gate unit, rg = tid>>7 -> 8 rows = 4 packed row-pairs).
__global__ void __launch_bounds__(NTHR, 2)
lstm_main(const float* __restrict__ x, const float* __restrict__ bd, float* __restrict__ out)
{
  __shared__ __align__(16) float uT [INW][PITCH];  // transposed step input
  __shared__ __align__(16) float h1T[H][PITCH];
  __shared__ __align__(16) float h2T[H][PITCH];

  const int tid   = threadIdx.x;
  const int k     = tid & 127;
  const int rg    = tid >> 7;
  const int rbase = rg * 8;
  const int row0  = blockIdx.x * BT;

  for (int i = tid; i < H * PITCH; i += NTHR) { (&h1T[0][0])[i] = 0.0f; (&h2T[0][0])[i] = 0.0f; }

  ull c1[4], c2[4];
  #pragma unroll
  for (int p = 0; p < 4; ++p) { c1[p] = 0ull; c2[p] = 0ull; }

  ull b0p[4], b1p[4];
  #pragma unroll
  for (int g = 0; g < 4; ++g) { b0p[g] = splat2(g_b0[g * H + k]); b1p[g] = splat2(g_b1[g * H + k]); }
  const float bdv = (k < OUTW) ? bd[k] : 0.0f;

  __syncthreads();

  for (int s = 0; s < NSTEP; ++s) {
    // ---- stage input u ----
    // s < 50: x[:, s, :].  s == 50: x[:, 49, :] again (also caches cond rows 66..85).
    // s > 50: uT[0..65] holds pose from previous dense; uT[66..85] keeps cond.
    if (s <= TSEQ) {
      int t = (s < TSEQ) ? s : (TSEQ - 1);
      for (int i = tid; i < BT * INW; i += NTHR) {
        int r = i / INW, c = i % INW;
        uT[c][r] = x[(size_t)(row0 + r) * (TSEQ * INW) + t * INW + c];
      }
    }
    __syncthreads();

    ull acc[4][4], hn[4];

    // ---- layer 0 : gates = u@Wih0^T + h1@Whh0^T + b0 ----
    #pragma unroll
    for (int g = 0; g < 4; ++g)
      #pragma unroll
      for (int p = 0; p < 4; ++p) acc[g][p] = b0p[g];
    accum<INW>(acc, g_W0i, &uT[0][0],  k, rbase);
    accum<H>  (acc, g_W0h, &h1T[0][0], k, rbase);
    cell_update(acc, c1, hn);
    __syncthreads();                      // all reads of old h1T done
    *reinterpret_cast<ulonglong2*>(&h1T[k][rbase])     = make_ulonglong2(hn[0], hn[1]);
    *reinterpret_cast<ulonglong2*>(&h1T[k][rbase + 4]) = make_ulonglong2(hn[2], hn[3]);
    __syncthreads();

    // ---- layer 1 : gates = h1@Wih1^T + h2@Whh1^T + b1 ----
    #pragma unroll
    for (int g = 0; g < 4; ++g)
      #pragma unroll
      for (int p = 0; p < 4; ++p) acc[g][p] = b1p[g];
    accum<H>(acc, g_W1i, &h1T[0][0], k, rbase);
    accum<H>(acc, g_W1h, &h2T[0][0], k, rbase);
    cell_update(acc, c2, hn);
    __syncthreads();                      // all reads of old h2T done
    *reinterpret_cast<ulonglong2*>(&h2T[k][rbase])     = make_ulonglong2(hn[0], hn[1]);
    *reinterpret_cast<ulonglong2*>(&h2T[k][rbase + 4]) = make_ulonglong2(hn[2], hn[3]);
    __syncthreads();

    // ---- dense head (steps 50..64): pose = h2 @ Wd^T + bd ----
    if (s >= TSEQ) {
      const int so = s - TSEQ;
      if (k < OUTW) {
        ull pa[4];
        #pragma unroll
        for (int p = 0; p < 4; ++p) pa[p] = splat2(bdv);
        #pragma unroll 4
        for (int kk = 0; kk < H; ++kk) {
          ull w2 = splat2(__ldg(&g_WdT[kk * OUTW + k]));
          const float* srow = &h2T[kk][rbase];
          ulonglong2 ua = *reinterpret_cast<const ulonglong2*>(srow);
          ulonglong2 ub = *reinterpret_cast<const ulonglong2*>(srow + 4);
          pa[0] = fma2(ua.x, w2, pa[0]);
          pa[1] = fma2(ua.y, w2, pa[1]);
          pa[2] = fma2(ub.x, w2, pa[2]);
          pa[3] = fma2(ub.y, w2, pa[3]);
        }
        #pragma unroll
        for (int p = 0; p < 4; ++p) {
          float2 f = unpack2(pa[p]);
          int rloc = rbase + 2 * p;
          size_t r = (size_t)(row0 + rloc);
          out[ r      * (RSTEPS * OUTW) + so * OUTW + k] = f.x;
          out[(r + 1) * (RSTEPS * OUTW) + so * OUTW + k] = f.y;
          uT[k][rloc]     = f.x;   // pose becomes next step's u[0..65]
          uT[k][rloc + 1] = f.y;
        }
      }
      __syncthreads();
    }
  }
}

extern "C" void kernel_launch(void* const* d_in, const int* in_sizes, int n_in,
                              void* d_out, int out_size)
{
  const float* x    = (const float*)d_in[0];
  const float* Wih0 = (const float*)d_in[1];
  const float* Whh0 = (const float*)d_in[2];
  const float* bih0 = (const float*)d_in[3];
  const float* bhh0 = (const float*)d_in[4];
  const float* Wih1 = (const float*)d_in[5];
  const float* Whh1 = (const float*)d_in[6];
  const float* bih1 = (const float*)d_in[7];
  const float* bhh1 = (const float*)d_in[8];
  const float* Wd   = (const float*)d_in[9];
  const float* bd   = (const float*)d_in[10];
  float* out = (float*)d_out;

  const int B = in_sizes[0] / (TSEQ * INW);   // 8192

  const int prep_n = GATES * INW + 3 * GATES * H + OUTW * H + 2 * GATES;
  prep_kernel<<<(prep_n + 255) / 256, 256>>>(Wih0, Whh0, bih0, bhh0,
                                             Wih1, Whh1, bih1, bhh1, Wd);
  lstm_main<<<B / BT, NTHR>>>(x, bd, out);
}